// round 7
// baseline (speedup 1.0000x reference)
#include <cuda_runtime.h>
#include <cstdint>

// Problem constants
#define NN 50000
#define EE 800000
#define ET (EE + NN)          // edges + self loops
#define HEADS 8
#define F 256                 // HEADS * 32 (same for both layers)

// ---------------- scratch (device globals; no allocation) ----------------
// __align__(16): accessed via float4 loads and red.global.add.v4.f32.
__device__ __align__(16) float    g_xl[(size_t)NN * F];       // lin_l(x)  [N,256]
__device__ __align__(16) float    g_xr[(size_t)NN * F];       // lin_r(x)  [N,256]
__device__ __align__(16) float    g_acc[(size_t)NN * F];      // per-head aggregation accumulator
__device__ __align__(16) float    g_sc[(size_t)ET * HEADS];   // edge scores, then unnorm attn a
__device__ unsigned g_smax[NN * HEADS];         // segment max (ordered-uint encoded)
__device__ float    g_denom[NN * HEADS];        // segment sum of exp
__device__ __align__(16) float    g_h[NN * 32]; // layer-1 output

// float <-> monotonic unsigned encoding (for atomicMax on floats incl. negatives)
__device__ __forceinline__ unsigned fenc(float f) {
    unsigned u = __float_as_uint(f);
    return (u & 0x80000000u) ? ~u : (u | 0x80000000u);
}
__device__ __forceinline__ float fdec(unsigned k) {
    return (k & 0x80000000u) ? __uint_as_float(k ^ 0x80000000u)
                             : __uint_as_float(~k);
}
#define ENC_NEG_INF 0x007FFFFFu   // fenc(-inf)

// vectorized fp32 reduction to global (sm_90+); p must be 16B aligned
__device__ __forceinline__ void red4(float* p, float a, float b, float c, float d) {
    asm volatile("red.global.add.v4.f32 [%0], {%1,%2,%3,%4};"
                 :: "l"(p), "f"(a), "f"(b), "f"(c), "f"(d) : "memory");
}

// ---------------- init: zero accumulators, reset softmax state ----------------
__global__ void init_kernel() {
    int idx = blockIdx.x * blockDim.x + threadIdx.x;
    int stride = gridDim.x * blockDim.x;
    for (int i = idx; i < NN * F; i += stride) g_acc[i] = 0.f;
    for (int i = idx; i < NN * HEADS; i += stride) {
        g_smax[i] = ENC_NEG_INF;
        g_denom[i] = 0.f;
    }
}

// ---------------- fused GEMM: xl = x@Wl^T+bl, xr = x@Wr^T+br ----------------
// 512 threads: t<256 -> l column t, t>=256 -> r column t-256.
// Weight row held in registers; x rows staged through smem, read as broadcast float4.
template <int K>
__global__ __launch_bounds__(512) void gemm_kernel(
    const float* __restrict__ xin,   // nullptr -> use g_h
    const float* __restrict__ Wl, const float* __restrict__ bl,
    const float* __restrict__ Wr, const float* __restrict__ br)
{
    const int TILE = 32;
    __shared__ __align__(16) float xs[TILE * K];
    const float* x = xin ? xin : g_h;

    int t   = threadIdx.x;
    int col = t & 255;
    const float* W = (t < 256) ? Wl : Wr;
    float* o       = (t < 256) ? g_xl : g_xr;
    float w[K];
#pragma unroll
    for (int k = 0; k < K; k += 4) {
        float4 v = *(const float4*)(W + col * K + k);
        w[k] = v.x; w[k + 1] = v.y; w[k + 2] = v.z; w[k + 3] = v.w;
    }
    float bias = ((t < 256) ? bl : br)[col];

    for (int row0 = blockIdx.x * TILE; row0 < NN; row0 += gridDim.x * TILE) {
        int nr = min(TILE, NN - row0);
        __syncthreads();
        for (int i = t; i < nr * K; i += 512) xs[i] = x[row0 * K + i];
        __syncthreads();
        for (int r = 0; r < nr; r++) {
            float a0 = 0.f, a1 = 0.f, a2 = 0.f, a3 = 0.f;
            const float4* xp = (const float4*)(xs + r * K);
#pragma unroll
            for (int k = 0; k < K / 4; k++) {
                float4 xv = xp[k];
                a0 += xv.x * w[4 * k];     a1 += xv.y * w[4 * k + 1];
                a2 += xv.z * w[4 * k + 2]; a3 += xv.w * w[4 * k + 3];
            }
            o[(size_t)(row0 + r) * F + col] = (a0 + a1) + (a2 + a3) + bias;
        }
    }
}

// ---------------- edge pass 1: scores + segment max ----------------
// Warp per edge. Lane l owns feature elements [8l, 8l+8) -> head l>>2.
// edge_index is int32 (harness dtype set is {float32, int32, bf16}).
__global__ __launch_bounds__(256) void edge_score_kernel(
    const int* __restrict__ ei, const float* __restrict__ att)
{
    int lane = threadIdx.x & 31;
    int gw = (blockIdx.x * blockDim.x + threadIdx.x) >> 5;
    int nw = (gridDim.x * blockDim.x) >> 5;
    float4 at0 = *((const float4*)att + lane * 2);
    float4 at1 = *((const float4*)att + lane * 2 + 1);

    for (int e = gw; e < ET; e += nw) {
        int s, d;
        if (e < EE) {
            s = ei[e]; d = ei[EE + e];
            if (s == d) continue;         // masked original self-loop (warp-uniform)
        } else {
            s = d = e - EE;               // fresh self loop, always valid
        }
        const float4* pl = (const float4*)(g_xl + (size_t)s * F) + lane * 2;
        const float4* pr = (const float4*)(g_xr + (size_t)d * F) + lane * 2;
        float4 l0 = pl[0], l1 = pl[1];
        float4 r0 = pr[0], r1 = pr[1];
        float p, v;
        v = l0.x + r0.x; p  = (v > 0.f ? v : 0.2f * v) * at0.x;
        v = l0.y + r0.y; p += (v > 0.f ? v : 0.2f * v) * at0.y;
        v = l0.z + r0.z; p += (v > 0.f ? v : 0.2f * v) * at0.z;
        v = l0.w + r0.w; p += (v > 0.f ? v : 0.2f * v) * at0.w;
        v = l1.x + r1.x; p += (v > 0.f ? v : 0.2f * v) * at1.x;
        v = l1.y + r1.y; p += (v > 0.f ? v : 0.2f * v) * at1.y;
        v = l1.z + r1.z; p += (v > 0.f ? v : 0.2f * v) * at1.z;
        v = l1.w + r1.w; p += (v > 0.f ? v : 0.2f * v) * at1.w;
        // reduce within 4-lane head group
        p += __shfl_xor_sync(0xFFFFFFFFu, p, 1);
        p += __shfl_xor_sync(0xFFFFFFFFu, p, 2);
        if ((lane & 3) == 0) {
            int h = lane >> 2;
            g_sc[(size_t)e * HEADS + h] = p;
            atomicMax(&g_smax[d * HEADS + h], fenc(p));
        }
    }
}

// ---------------- edge pass 2: a = exp(score - smax); denom += a ----------------
__global__ __launch_bounds__(256) void edge_exp_kernel(const int* __restrict__ ei)
{
    int idx = blockIdx.x * blockDim.x + threadIdx.x;
    if (idx >= ET * HEADS) return;
    int e = idx >> 3, h = idx & 7;
    int d; bool valid;
    if (e < EE) {
        int s = ei[e]; d = ei[EE + e];
        valid = (s != d);
    } else { d = e - EE; valid = true; }
    float a = 0.f;
    if (valid) {
        float sc = g_sc[idx];
        float mx = fdec(g_smax[d * HEADS + h]);
        a = __expf(sc - mx);
        atomicAdd(&g_denom[d * HEADS + h], a);
    }
    g_sc[idx] = a;
}

// ---------------- edge pass 3: acc[dst] += a * xl[src] ----------------
__global__ __launch_bounds__(256) void edge_agg_kernel(const int* __restrict__ ei)
{
    int lane = threadIdx.x & 31;
    int gw = (blockIdx.x * blockDim.x + threadIdx.x) >> 5;
    int nw = (gridDim.x * blockDim.x) >> 5;
    for (int e = gw; e < ET; e += nw) {
        int s, d;
        if (e < EE) {
            s = ei[e]; d = ei[EE + e];
            if (s == d) continue;
        } else {
            s = d = e - EE;
        }
        float a8 = 0.f;
        if (lane < 8) a8 = g_sc[(size_t)e * HEADS + lane];
        float a = __shfl_sync(0xFFFFFFFFu, a8, lane >> 2);
        const float4* pl = (const float4*)(g_xl + (size_t)s * F) + lane * 2;
        float4 v0 = pl[0], v1 = pl[1];
        float* po = g_acc + (size_t)d * F + lane * 8;
        red4(po,     a * v0.x, a * v0.y, a * v0.z, a * v0.w);
        red4(po + 4, a * v1.x, a * v1.y, a * v1.z, a * v1.w);
    }
}

// ---------------- node finalize: normalize, mean over heads, bias, activation ----------------
__global__ __launch_bounds__(256) void node_final_kernel(
    const float* __restrict__ bias, float* __restrict__ outp, int act)
{
    int idx = blockIdx.x * blockDim.x + threadIdx.x;
    if (idx >= NN * 32) return;
    int i = idx >> 5, c = idx & 31;
    float* o = outp ? outp : g_h;
    float s = 0.f;
#pragma unroll
    for (int h = 0; h < HEADS; h++) {
        float den = fmaxf(g_denom[i * HEADS + h], 1e-16f);
        s += g_acc[(size_t)i * F + h * 32 + c] * __frcp_rn(den);
    }
    s = s * 0.125f + bias[c];
    if (act && s < 0.f) s *= 0.01f;
    o[idx] = s;
}

// ---------------- launch ----------------
extern "C" void kernel_launch(void* const* d_in, const int* in_sizes, int n_in,
                              void* d_out, int out_size)
{
    const float* x     = (const float*)d_in[0];
    const int*   ei    = (const int*)d_in[1];     // int32: harness has no int64 path
    const float* W1l   = (const float*)d_in[2];
    const float* b1l   = (const float*)d_in[3];
    const float* W1r   = (const float*)d_in[4];
    const float* b1r   = (const float*)d_in[5];
    const float* att1  = (const float*)d_in[6];
    const float* bias1 = (const float*)d_in[7];
    const float* W2l   = (const float*)d_in[8];
    const float* b2l   = (const float*)d_in[9];
    const float* W2r   = (const float*)d_in[10];
    const float* b2r   = (const float*)d_in[11];
    const float* att2  = (const float*)d_in[12];
    const float* bias2 = (const float*)d_in[13];
    float* out = (float*)d_out;

    const int EB = 4096;                               // edge-kernel blocks (warp/edge grid-stride)
    const int XB = (ET * HEADS + 255) / 256;           // edge_exp blocks
    const int NB = (NN * 32 + 255) / 256;              // node_final blocks

    // ---- layer 1 ----
    init_kernel<<<2048, 256>>>();
    gemm_kernel<64><<<296, 512>>>(x, W1l, b1l, W1r, b1r);
    edge_score_kernel<<<EB, 256>>>(ei, att1);
    edge_exp_kernel<<<XB, 256>>>(ei);
    edge_agg_kernel<<<EB, 256>>>(ei);
    node_final_kernel<<<NB, 256>>>(bias1, nullptr, 1);   // -> g_h, leaky 0.01

    // ---- layer 2 ----
    init_kernel<<<2048, 256>>>();
    gemm_kernel<32><<<296, 512>>>(nullptr, W2l, b2l, W2r, b2r);
    edge_score_kernel<<<EB, 256>>>(ei, att2);
    edge_exp_kernel<<<XB, 256>>>(ei);
    edge_agg_kernel<<<EB, 256>>>(ei);
    node_final_kernel<<<NB, 256>>>(bias2, out, 0);       // -> d_out
}

// round 8
// speedup vs baseline: 2.2098x; 2.2098x over previous
#include <cuda_runtime.h>
#include <cstdint>

// Problem constants
#define NN 50000
#define EE 800000
#define ET (EE + NN)          // edges + fresh self loops
#define HEADS 8
#define F 256                 // HEADS * 32 (same for both layers)
#define SCAN_T 1024
#define SCAN_CH ((NN + SCAN_T - 1) / SCAN_T)   // 49

// ---------------- scratch (device globals; no allocation) ----------------
__device__ __align__(16) float g_xl[(size_t)NN * F];   // lin_l(x)  [N,256]
__device__ __align__(16) float g_xr[(size_t)NN * F];   // lin_r(x)  [N,256]
__device__ __align__(16) float g_h[NN * 32];           // layer-1 output
__device__ int g_deg[NN];     // in-degree (incl. self loop)
__device__ int g_off[NN];     // CSR row start (exclusive scan of deg)
__device__ int g_pos[NN];     // fill cursor
__device__ int g_csr[ET];     // src node per CSR slot

#define NEG_INF (-__int_as_float(0x7f800000))

// ---------------- CSR build (graph identical for both layers) ----------------
__global__ void deg_init_kernel() {
    int i = blockIdx.x * blockDim.x + threadIdx.x;
    if (i < NN) g_deg[i] = 1;                 // fresh self loop
}

__global__ void deg_count_kernel(const int* __restrict__ ei) {
    int e = blockIdx.x * blockDim.x + threadIdx.x;
    if (e >= EE) return;
    int s = ei[e], d = ei[EE + e];
    if (s != d) atomicAdd(&g_deg[d], 1);      // original self loops masked
}

// single-block exclusive scan of g_deg -> g_off, g_pos
__global__ __launch_bounds__(SCAN_T) void scan_kernel() {
    __shared__ int sh[SCAN_T];
    int t = threadIdx.x;
    int base = t * SCAN_CH;
    int sum = 0;
#pragma unroll 4
    for (int j = 0; j < SCAN_CH; j++) {
        int idx = base + j;
        if (idx < NN) sum += g_deg[idx];
    }
    sh[t] = sum;
    __syncthreads();
    // Hillis-Steele inclusive scan
    for (int ofs = 1; ofs < SCAN_T; ofs <<= 1) {
        int v = (t >= ofs) ? sh[t - ofs] : 0;
        __syncthreads();
        sh[t] += v;
        __syncthreads();
    }
    int run = sh[t] - sum;                    // exclusive prefix for this chunk
    for (int j = 0; j < SCAN_CH; j++) {
        int idx = base + j;
        if (idx < NN) {
            g_off[idx] = run;
            g_pos[idx] = run;
            run += g_deg[idx];
        }
    }
}

__global__ void csr_fill_kernel(const int* __restrict__ ei) {
    int e = blockIdx.x * blockDim.x + threadIdx.x;
    if (e >= ET) return;
    int s, d;
    if (e < EE) {
        s = ei[e]; d = ei[EE + e];
        if (s == d) return;                   // masked original self loop
    } else {
        s = d = e - EE;                       // fresh self loop
    }
    int slot = atomicAdd(&g_pos[d], 1);
    g_csr[slot] = s;
}

// ---------------- fused GEMM: xl = x@Wl^T+bl, xr = x@Wr^T+br ----------------
// 512 threads: t<256 -> l column t, t>=256 -> r column t-256.
template <int K>
__global__ __launch_bounds__(512) void gemm_kernel(
    const float* __restrict__ xin,   // nullptr -> use g_h
    const float* __restrict__ Wl, const float* __restrict__ bl,
    const float* __restrict__ Wr, const float* __restrict__ br)
{
    const int TILE = 32;
    __shared__ __align__(16) float xs[TILE * K];
    const float* x = xin ? xin : g_h;

    int t   = threadIdx.x;
    int col = t & 255;
    const float* W = (t < 256) ? Wl : Wr;
    float* o       = (t < 256) ? g_xl : g_xr;
    float w[K];
#pragma unroll
    for (int k = 0; k < K; k += 4) {
        float4 v = *(const float4*)(W + col * K + k);
        w[k] = v.x; w[k + 1] = v.y; w[k + 2] = v.z; w[k + 3] = v.w;
    }
    float bias = ((t < 256) ? bl : br)[col];

    for (int row0 = blockIdx.x * TILE; row0 < NN; row0 += gridDim.x * TILE) {
        int nr = min(TILE, NN - row0);
        __syncthreads();
        for (int i = t; i < nr * K; i += 512) xs[i] = x[row0 * K + i];
        __syncthreads();
        for (int r = 0; r < nr; r++) {
            float a0 = 0.f, a1 = 0.f, a2 = 0.f, a3 = 0.f;
            const float4* xp = (const float4*)(xs + r * K);
#pragma unroll
            for (int k = 0; k < K / 4; k++) {
                float4 xv = xp[k];
                a0 += xv.x * w[4 * k];     a1 += xv.y * w[4 * k + 1];
                a2 += xv.z * w[4 * k + 2]; a3 += xv.w * w[4 * k + 3];
            }
            o[(size_t)(row0 + r) * F + col] = (a0 + a1) + (a2 + a3) + bias;
        }
    }
}

// ---------------- fused per-node attention: warp per dst node ----------------
// Lane l owns feature channels [8l, 8l+8) == head (l>>2), offsets (l&3)*8..+8.
// Online softmax over the node's CSR edge list; accumulators in registers.
__global__ __launch_bounds__(256) void node_attn_kernel(
    const float* __restrict__ att, const float* __restrict__ bias,
    float* __restrict__ outp,      // nullptr -> g_h
    int act)
{
    int lane = threadIdx.x & 31;
    int node = (blockIdx.x * blockDim.x + threadIdx.x) >> 5;
    if (node >= NN) return;

    float4 at0 = *((const float4*)att + lane * 2);
    float4 at1 = *((const float4*)att + lane * 2 + 1);

    // xr[dst] once per node
    const float4* pr = (const float4*)(g_xr + (size_t)node * F) + lane * 2;
    float4 r0 = pr[0], r1 = pr[1];

    int beg = g_off[node];
    int end = beg + g_deg[node];

    float m = NEG_INF, denom = 0.f;
    float ac[8];
#pragma unroll
    for (int j = 0; j < 8; j++) ac[j] = 0.f;

    for (int k = beg; k < end; k++) {
        int s = __ldg(&g_csr[k]);             // warp-uniform broadcast
        const float4* pl = (const float4*)(g_xl + (size_t)s * F) + lane * 2;
        float4 l0 = pl[0], l1 = pl[1];
        float p, v;
        v = l0.x + r0.x; p  = (v > 0.f ? v : 0.2f * v) * at0.x;
        v = l0.y + r0.y; p += (v > 0.f ? v : 0.2f * v) * at0.y;
        v = l0.z + r0.z; p += (v > 0.f ? v : 0.2f * v) * at0.z;
        v = l0.w + r0.w; p += (v > 0.f ? v : 0.2f * v) * at0.w;
        v = l1.x + r1.x; p += (v > 0.f ? v : 0.2f * v) * at1.x;
        v = l1.y + r1.y; p += (v > 0.f ? v : 0.2f * v) * at1.y;
        v = l1.z + r1.z; p += (v > 0.f ? v : 0.2f * v) * at1.z;
        v = l1.w + r1.w; p += (v > 0.f ? v : 0.2f * v) * at1.w;
        // butterfly within 4-lane head group: every lane gets full head score
        p += __shfl_xor_sync(0xFFFFFFFFu, p, 1);
        p += __shfl_xor_sync(0xFFFFFFFFu, p, 2);
        // online softmax update
        float mn = fmaxf(m, p);
        float c  = __expf(m - mn);            // exp(-inf - finite) = 0 on first edge
        float w  = __expf(p - mn);
        denom = denom * c + w;
        ac[0] = ac[0] * c + w * l0.x;
        ac[1] = ac[1] * c + w * l0.y;
        ac[2] = ac[2] * c + w * l0.z;
        ac[3] = ac[3] * c + w * l0.w;
        ac[4] = ac[4] * c + w * l1.x;
        ac[5] = ac[5] * c + w * l1.y;
        ac[6] = ac[6] * c + w * l1.z;
        ac[7] = ac[7] * c + w * l1.w;
        m = mn;
    }

    float inv = __frcp_rn(fmaxf(denom, 1e-16f));
#pragma unroll
    for (int j = 0; j < 8; j++) {
        float v = ac[j] * inv;
        // sum over the 8 heads: butterfly across lanes with stride 4, 8, 16
        v += __shfl_xor_sync(0xFFFFFFFFu, v, 4);
        v += __shfl_xor_sync(0xFFFFFFFFu, v, 8);
        v += __shfl_xor_sync(0xFFFFFFFFu, v, 16);
        ac[j] = v;
    }

    if (lane < 4) {
        float* o = (outp ? outp : g_h) + (size_t)node * 32 + lane * 8;
#pragma unroll
        for (int j = 0; j < 8; j++) {
            float s = ac[j] * 0.125f + bias[lane * 8 + j];
            if (act && s < 0.f) s *= 0.01f;
            o[j] = s;
        }
    }
}

// ---------------- launch ----------------
extern "C" void kernel_launch(void* const* d_in, const int* in_sizes, int n_in,
                              void* d_out, int out_size)
{
    const float* x     = (const float*)d_in[0];
    const int*   ei    = (const int*)d_in[1];     // int32 (harness dtype set)
    const float* W1l   = (const float*)d_in[2];
    const float* b1l   = (const float*)d_in[3];
    const float* W1r   = (const float*)d_in[4];
    const float* b1r   = (const float*)d_in[5];
    const float* att1  = (const float*)d_in[6];
    const float* bias1 = (const float*)d_in[7];
    const float* W2l   = (const float*)d_in[8];
    const float* b2l   = (const float*)d_in[9];
    const float* W2r   = (const float*)d_in[10];
    const float* b2r   = (const float*)d_in[11];
    const float* att2  = (const float*)d_in[12];
    const float* bias2 = (const float*)d_in[13];
    float* out = (float*)d_out;

    const int NB  = (NN + 255) / 256;
    const int EB  = (EE + 255) / 256;
    const int TB  = (ET + 255) / 256;
    const int AB  = (NN * 32 + 255) / 256;    // warp/node: 8 nodes per 256-thr block

    // ---- CSR build (shared by both layers) ----
    deg_init_kernel<<<NB, 256>>>();
    deg_count_kernel<<<EB, 256>>>(ei);
    scan_kernel<<<1, SCAN_T>>>();
    csr_fill_kernel<<<TB, 256>>>(ei);

    // ---- layer 1 ----
    gemm_kernel<64><<<296, 512>>>(x, W1l, b1l, W1r, b1r);
    node_attn_kernel<<<AB, 256>>>(att1, bias1, nullptr, 1);   // -> g_h, leaky 0.01

    // ---- layer 2 ----
    gemm_kernel<32><<<296, 512>>>(nullptr, W2l, b2l, W2r, b2r);
    node_attn_kernel<<<AB, 256>>>(att2, bias2, out, 0);       // -> d_out
}